// round 9
// baseline (speedup 1.0000x reference)
#include <cuda_runtime.h>
#include <cuda_fp16.h>
#include <math.h>

#define B_  16
#define L_  4096
#define E_  128
#define F_  256
#define Y_  1000
#define YP_ 1024
#define MP_ 2048             /* padded attn M */

#define BM  128
#define BN  128
#define BK  64               /* halves per K chunk */
#define SROWH 72             /* smem row stride in halves (144B, conflict-free) */

/* conv kernel smem (A+B, 3 stages) */
#define CV_STAGEH (BM * SROWH)
#define CV_NSTAGE 3
#define CV_SMEM (2 * CV_NSTAGE * CV_STAGEH * 2)   /* 110592 B */

/* attn kernel smem (B only, 4 stages) */
#define AT_STAGEH (BN * SROWH)
#define AT_NSTAGE 4
#define AT_SMEM (AT_NSTAGE * AT_STAGEH * 2)       /* 73728 B */

// Scratch (static __device__ arrays; allocation-free per harness rules)
__device__ __align__(128) __half g_embH[(size_t)B_ * L_ * E_];  // fp16 embeddings
__device__ __align__(128) __half g_wH  [3 * F_ * E_];           // fp16 conv_w [kw][f][e]
__device__ __align__(128) __half g_hcH [(size_t)B_ * L_ * F_];  // conv out fp16 [b][l][f]
__device__ __align__(128) uint4  g_w2F [16 * 16 * 8 * 32];      // A fragments, 1 MB
__device__ __align__(128) float  g_part[(size_t)B_ * YP_ * 64 * 3]; // (m,Z,S) partials
__device__ float g_nll[B_];

// ---------------------------------------------------------------------------
__device__ __forceinline__ unsigned smem_u32(const void* p) {
    unsigned a;
    asm("{ .reg .u64 t; cvta.to.shared.u64 t, %1; cvt.u32.u64 %0, t; }"
        : "=r"(a) : "l"(p));
    return a;
}
__device__ __forceinline__ void cp_async16(unsigned dst, const void* src, int src_bytes) {
    asm volatile("cp.async.cg.shared.global [%0], [%1], 16, %2;"
                 :: "r"(dst), "l"(src), "r"(src_bytes));
}
__device__ __forceinline__ void cp_commit() {
    asm volatile("cp.async.commit_group;");
}
__device__ __forceinline__ void ldsm4(unsigned* r, unsigned addr) {
    asm volatile("ldmatrix.sync.aligned.m8n8.x4.shared.b16 {%0,%1,%2,%3}, [%4];"
                 : "=r"(r[0]), "=r"(r[1]), "=r"(r[2]), "=r"(r[3]) : "r"(addr));
}
__device__ __forceinline__ void mma16816(float* d, const unsigned* a, const unsigned* b) {
    asm volatile(
        "mma.sync.aligned.m16n8k16.row.col.f32.f16.f16.f32 "
        "{%0,%1,%2,%3}, {%4,%5,%6,%7}, {%8,%9}, {%0,%1,%2,%3};"
        : "+f"(d[0]), "+f"(d[1]), "+f"(d[2]), "+f"(d[3])
        : "r"(a[0]), "r"(a[1]), "r"(a[2]), "r"(a[3]), "r"(b[0]), "r"(b[1]));
}

// ---------------------------------------------------------------------------
// Kernel 1: embedding gather -> fp16
// ---------------------------------------------------------------------------
__global__ void embed_kernel(const int* __restrict__ x,
                             const float* __restrict__ embed_w)
{
    int b = blockIdx.y;
    int l = blockIdx.x * 8 + (threadIdx.x >> 5);
    int q = threadIdx.x & 31;
    int xi = x[b * L_ + l];
    float4 v = ((const float4*)(embed_w + (size_t)xi * E_))[q];
    __half2 h01 = __floats2half2_rn(v.x, v.y);
    __half2 h23 = __floats2half2_rn(v.z, v.w);
    uint2 u;
    u.x = *(unsigned*)&h01;
    u.y = *(unsigned*)&h23;
    ((uint2*)(g_embH + ((size_t)b * L_ + l) * E_))[q] = u;
}

// ---------------------------------------------------------------------------
// Kernel 2a: conv_w transpose+round (F,E,3) -> wH[kw][f][e]
// ---------------------------------------------------------------------------
__global__ void wtrans_kernel(const float* __restrict__ conv_w)
{
    int i = blockIdx.x * 256 + threadIdx.x;
    if (i < F_ * E_) {
        int f = i / E_, e = i % E_;
        #pragma unroll
        for (int kw = 0; kw < 3; kw++)
            g_wH[((size_t)kw * F_ + f) * E_ + e] =
                __float2half_rn(conv_w[((size_t)f * E_ + e) * 3 + kw]);
    }
}

// ---------------------------------------------------------------------------
// Kernel 2b: attn A-matrix in FRAGMENT order.
// Logical A row r: even r -> U_w[r/2], odd r -> fc_w[r/2], zero for r>=2000.
// g_w2F[((mt*16 + k16)*8 + wr)*32 + ln] = {A(r0,c0|c0+1), A(r1,c0|c0+1),
//                                          A(r0,c0+8|9),  A(r1,c0+8|9)}
// with r0 = mt*128 + wr*16 + (ln>>2), r1 = r0+8, c0 = k16*16 + (ln&3)*2.
// Matches ldmatrix.x4 register order {r0c0, r1c0, r0c8, r1c8}.
// ---------------------------------------------------------------------------
__global__ void wfrag_kernel(const float* __restrict__ U_w,
                             const float* __restrict__ fc_w)
{
    int i = blockIdx.x * 256 + threadIdx.x;   // 65536 total
    int ln  = i & 31;
    int wr  = (i >> 5) & 7;
    int k16 = (i >> 8) & 15;
    int mt  = i >> 12;
    int gg  = ln >> 2, tg = ln & 3;
    int r0 = mt * 128 + wr * 16 + gg;
    int r1 = r0 + 8;
    int c0 = k16 * 16 + tg * 2;

    float v[8];
    #pragma unroll
    for (int q = 0; q < 8; q++) {
        int r = (q & 1) ? r1 : r0;          // q: bit0 = row sel
        int c = c0 + ((q >> 2) ? 8 : 0) + ((q >> 1) & 1);
        if (r >= 2 * Y_) { v[q] = 0.f; continue; }
        const float* s = (r & 1) ? fc_w : U_w;
        v[q] = s[(size_t)(r >> 1) * F_ + c];
    }
    // pack: reg0 = (r0,c0),(r0,c0+1); reg1 = (r1,c0),(r1,c0+1);
    //       reg2 = (r0,c0+8),(r0,c0+9); reg3 = (r1,c0+8),(r1,c0+9)
    __half2 p0 = __floats2half2_rn(v[0], v[2]);
    __half2 p1 = __floats2half2_rn(v[1], v[3]);
    __half2 p2 = __floats2half2_rn(v[4], v[6]);
    __half2 p3 = __floats2half2_rn(v[5], v[7]);
    uint4 u;
    u.x = *(unsigned*)&p0; u.y = *(unsigned*)&p1;
    u.z = *(unsigned*)&p2; u.w = *(unsigned*)&p3;
    g_w2F[i] = u;
}

// ---------------------------------------------------------------------------
// Kernel 3: conv GEMM (R8-proven): 128x128 tile, 8 warps, BK=64, 3-stage.
// C[l,f] = sum_kw sum_e embH[l+kw-1,e]*wH[kw][f][e]; +bias, relu -> hcH
// ---------------------------------------------------------------------------
__global__ __launch_bounds__(256)
void conv_kernel(const float* __restrict__ bias)
{
    extern __shared__ __align__(16) char smem[];
    unsigned aBase = smem_u32(smem);
    unsigned bBase = aBase + CV_NSTAGE * CV_STAGEH * 2;

    int tid  = threadIdx.x;
    int wid  = tid >> 5, lane = tid & 31;
    int g    = lane >> 2, tig = lane & 3;
    int lq   = lane >> 3, lr  = lane & 7;
    int wm   = wid >> 1,  wn  = wid & 1;
    int b    = blockIdx.z;
    int m0   = blockIdx.x * BM, n0 = blockIdx.y * BN;
    const int nchunks = 6;

    int lrow  = tid >> 1;
    int lcolh = (tid & 1) * 32;

    float d[2][8][4];
    #pragma unroll
    for (int mi = 0; mi < 2; mi++)
        #pragma unroll
        for (int ni = 0; ni < 8; ni++)
            #pragma unroll
            for (int q = 0; q < 4; q++) d[mi][ni][q] = 0.0f;

    auto prefetch = [&](int c) {
        int st = c % CV_NSTAGE;
        int kw = c >> 1, ek = (c & 1) * BK;
        int lsrc = m0 + lrow + kw - 1;
        bool av = ((unsigned)lsrc < (unsigned)L_);
        int abytes = av ? 16 : 0;
        const __half* ap = g_embH + ((size_t)b * L_ + (av ? lsrc : 0)) * E_ + ek + lcolh;
        const __half* bp = g_wH + ((size_t)kw * F_ + n0 + lrow) * E_ + ek + lcolh;
        unsigned da = aBase + (st * CV_STAGEH + lrow * SROWH + lcolh) * 2;
        unsigned db = bBase + (st * CV_STAGEH + lrow * SROWH + lcolh) * 2;
        #pragma unroll
        for (int j = 0; j < 4; j++) {
            cp_async16(da + j * 16, ap + j * 8, abytes);
            cp_async16(db + j * 16, bp + j * 8, 16);
        }
    };

    prefetch(0); cp_commit();
    prefetch(1); cp_commit();

    unsigned aOffs[2], bOffs[4];
    #pragma unroll
    for (int mi = 0; mi < 2; mi++) {
        int row = wm * 32 + mi * 16 + (lq & 1) * 8 + lr;
        aOffs[mi] = (row * SROWH + (lq >> 1) * 8) * 2;
    }
    #pragma unroll
    for (int ti = 0; ti < 4; ti++) {
        int row = wn * 64 + ti * 16 + (lq >> 1) * 8 + lr;
        bOffs[ti] = (row * SROWH + (lq & 1) * 8) * 2;
    }

    for (int c = 0; c < nchunks; c++) {
        if (c + 1 < nchunks) asm volatile("cp.async.wait_group 1;");
        else                 asm volatile("cp.async.wait_group 0;");
        __syncthreads();
        if (c + 2 < nchunks) { prefetch(c + 2); cp_commit(); }

        int st = c % CV_NSTAGE;
        unsigned Ab = aBase + st * CV_STAGEH * 2;
        unsigned Bb = bBase + st * CV_STAGEH * 2;

        #pragma unroll
        for (int kk = 0; kk < 4; kk++) {
            unsigned af[2][4];
            #pragma unroll
            for (int mi = 0; mi < 2; mi++)
                ldsm4(af[mi], Ab + aOffs[mi] + kk * 32);
            unsigned bf[4][4];
            #pragma unroll
            for (int ti = 0; ti < 4; ti++)
                ldsm4(bf[ti], Bb + bOffs[ti] + kk * 32);
            #pragma unroll
            for (int mi = 0; mi < 2; mi++)
                #pragma unroll
                for (int ni = 0; ni < 8; ni++)
                    mma16816(d[mi][ni], af[mi], &bf[ni >> 1][(ni & 1) * 2]);
        }
    }

    #pragma unroll
    for (int mi = 0; mi < 2; mi++) {
        int row = m0 + wm * 32 + mi * 16 + g;
        #pragma unroll
        for (int ni = 0; ni < 8; ni++) {
            int col = n0 + wn * 64 + ni * 8 + tig * 2;
            float b0 = bias[col], b1 = bias[col + 1];
            __half2 v0 = __floats2half2_rn(fmaxf(d[mi][ni][0] + b0, 0.f),
                                           fmaxf(d[mi][ni][1] + b1, 0.f));
            __half2 v1 = __floats2half2_rn(fmaxf(d[mi][ni][2] + b0, 0.f),
                                           fmaxf(d[mi][ni][3] + b1, 0.f));
            *(__half2*)(g_hcH + ((size_t)b * L_ + row) * F_ + col)     = v0;
            *(__half2*)(g_hcH + ((size_t)b * L_ + row + 8) * F_ + col) = v1;
        }
    }
}

// ---------------------------------------------------------------------------
// Kernel 4: attn GEMM. A fragments via direct LDG.128 (g_w2F), B via smem
// ldsm (4-stage cp.async ring). Fused online-softmax partials in epilogue.
// C[m,l] = A[m,:] . hcH[l,:], K=256 (4 chunks of 64).
// ---------------------------------------------------------------------------
__global__ __launch_bounds__(256)
void attn_kernel()
{
    extern __shared__ __align__(16) char smem[];
    unsigned bBase = smem_u32(smem);

    int tid  = threadIdx.x;
    int wid  = tid >> 5, lane = tid & 31;
    int g    = lane >> 2, tig = lane & 3;
    int lq   = lane >> 3, lr  = lane & 7;
    int wm   = wid >> 1,  wn  = wid & 1;
    int b    = blockIdx.z;
    int m0   = blockIdx.y * BM, n0 = blockIdx.x * BN;
    const int nchunks = 4;

    // A fragment base: g_w2F[mt][k16][wr][lane]
    const uint4* aF = g_w2F + (size_t)blockIdx.y * (16 * 8 * 32);
    int aIdx = (wm * 2) * 32 + lane;   // +32 for mi=1; +(k16)*256 per k-step

    int lrow  = tid >> 1;
    int lcolh = (tid & 1) * 32;

    float d[2][8][4];
    #pragma unroll
    for (int mi = 0; mi < 2; mi++)
        #pragma unroll
        for (int ni = 0; ni < 8; ni++)
            #pragma unroll
            for (int q = 0; q < 4; q++) d[mi][ni][q] = 0.0f;

    auto prefetchB = [&](int c) {
        int st = c % AT_NSTAGE;
        const __half* bp = g_hcH + ((size_t)b * L_ + n0 + lrow) * F_ + c * BK + lcolh;
        unsigned db = bBase + (st * AT_STAGEH + lrow * SROWH + lcolh) * 2;
        #pragma unroll
        for (int j = 0; j < 4; j++)
            cp_async16(db + j * 16, bp + j * 8, 16);
    };

    prefetchB(0); cp_commit();
    prefetchB(1); cp_commit();

    unsigned bOffs[4];
    #pragma unroll
    for (int ti = 0; ti < 4; ti++) {
        int row = wn * 64 + ti * 16 + (lq >> 1) * 8 + lr;
        bOffs[ti] = (row * SROWH + (lq & 1) * 8) * 2;
    }

    for (int c = 0; c < nchunks; c++) {
        if (c + 1 < nchunks) asm volatile("cp.async.wait_group 1;");
        else                 asm volatile("cp.async.wait_group 0;");
        __syncthreads();
        if (c + 2 < nchunks) { prefetchB(c + 2); cp_commit(); }

        unsigned Bb = bBase + (c % AT_NSTAGE) * AT_STAGEH * 2;

        #pragma unroll
        for (int kk = 0; kk < 4; kk++) {
            int k16 = c * 4 + kk;
            uint4 a0 = __ldg(&aF[k16 * 256 + aIdx]);
            uint4 a1 = __ldg(&aF[k16 * 256 + aIdx + 32]);
            unsigned af0[4] = {a0.x, a0.y, a0.z, a0.w};
            unsigned af1[4] = {a1.x, a1.y, a1.z, a1.w};
            unsigned bf[4][4];
            #pragma unroll
            for (int ti = 0; ti < 4; ti++)
                ldsm4(bf[ti], Bb + bOffs[ti] + kk * 32);
            #pragma unroll
            for (int ni = 0; ni < 8; ni++) {
                mma16816(d[0][ni], af0, &bf[ni >> 1][(ni & 1) * 2]);
                mma16816(d[1][ni], af1, &bf[ni >> 1][(ni & 1) * 2]);
            }
        }
    }

    // fused online-softmax partials (rows interleaved: even=s, odd=t)
    int p = blockIdx.x * 2 + wn;        // 64-l chunk index (0..63)
    #pragma unroll
    for (int mi = 0; mi < 2; mi++) {
        float td[8][4];
        #pragma unroll
        for (int ni = 0; ni < 8; ni++)
            #pragma unroll
            for (int q = 0; q < 4; q++)
                td[ni][q] = __shfl_down_sync(0xFFFFFFFFu, d[mi][ni][q], 4);

        if ((g & 1) == 0) {
            #pragma unroll
            for (int h = 0; h < 2; h++) {
                float mm = -1e30f, Z = 0.f, S = 0.f;
                #pragma unroll
                for (int ni = 0; ni < 8; ni++) {
                    #pragma unroll
                    for (int cq = 0; cq < 2; cq++) {
                        float sv = d[mi][ni][h * 2 + cq];
                        float tv = td[ni][h * 2 + cq];
                        if (sv > mm) {
                            float r = __expf(mm - sv);
                            Z *= r; S *= r; mm = sv;
                        }
                        float e = __expf(sv - mm);
                        Z += e; S += e * tv;
                    }
                }
                const unsigned qmask = 0x0F0F0F0Fu;
                #pragma unroll
                for (int off = 1; off <= 2; off <<= 1) {
                    float m2 = __shfl_xor_sync(qmask, mm, off);
                    float Z2 = __shfl_xor_sync(qmask, Z, off);
                    float S2 = __shfl_xor_sync(qmask, S, off);
                    float mn = fmaxf(mm, m2);
                    float r1 = __expf(mm - mn), r2 = __expf(m2 - mn);
                    Z = Z * r1 + Z2 * r2;
                    S = S * r1 + S2 * r2;
                    mm = mn;
                }
                if (tig == 0) {
                    int y = (m0 + wm * 32 + mi * 16 + g + 8 * h) >> 1;
                    float* dst = g_part + ((size_t)(b * YP_ + y) * 64 + p) * 3;
                    dst[0] = mm; dst[1] = Z; dst[2] = S;
                }
            }
        }
    }
}

// ---------------------------------------------------------------------------
// Kernel 5: merge 64 softmax partials per (b,y) -> logits
// ---------------------------------------------------------------------------
__global__ void part_reduce_kernel(const float* __restrict__ fc_b,
                                   float* __restrict__ out_logit)
{
    int idx = blockIdx.x;
    int b = idx / Y_, y = idx % Y_;
    const float* pp = g_part + ((size_t)(b * YP_ + y) * 64) * 3;
    int lane = threadIdx.x;

    float m = pp[lane * 3], Z = pp[lane * 3 + 1], S = pp[lane * 3 + 2];
    {
        float m2 = pp[(lane + 32) * 3], Z2 = pp[(lane + 32) * 3 + 1], S2 = pp[(lane + 32) * 3 + 2];
        float mn = fmaxf(m, m2);
        float r1 = __expf(m - mn), r2 = __expf(m2 - mn);
        Z = Z * r1 + Z2 * r2; S = S * r1 + S2 * r2; m = mn;
    }
    #pragma unroll
    for (int off = 16; off; off >>= 1) {
        float m2 = __shfl_xor_sync(0xFFFFFFFFu, m, off);
        float Z2 = __shfl_xor_sync(0xFFFFFFFFu, Z, off);
        float S2 = __shfl_xor_sync(0xFFFFFFFFu, S, off);
        float mn = fmaxf(m, m2);
        float r1 = __expf(m - mn), r2 = __expf(m2 - mn);
        Z = Z * r1 + Z2 * r2; S = S * r1 + S2 * r2; m = mn;
    }
    if (lane == 0) out_logit[b * Y_ + y] = S / Z + fc_b[y];
}

// ---------------------------------------------------------------------------
// Kernel 6a/6b: cross-entropy loss (per-batch + merge)
// ---------------------------------------------------------------------------
__global__ void nll_kernel(const float* __restrict__ logit,
                           const int* __restrict__ target)
{
    __shared__ float red[256];
    int b = blockIdx.x;
    int tid = threadIdx.x;
    const float* lr = logit + b * Y_;

    float mx = -1e30f;
    for (int i = tid; i < Y_; i += 256) mx = fmaxf(mx, lr[i]);
    red[tid] = mx; __syncthreads();
    for (int s = 128; s; s >>= 1) {
        if (tid < s) red[tid] = fmaxf(red[tid], red[tid + s]);
        __syncthreads();
    }
    mx = red[0]; __syncthreads();

    float se = 0.0f;
    for (int i = tid; i < Y_; i += 256) se += expf(lr[i] - mx);
    red[tid] = se; __syncthreads();
    for (int s = 128; s; s >>= 1) {
        if (tid < s) red[tid] += red[tid + s];
        __syncthreads();
    }
    if (tid == 0)
        g_nll[b] = -(lr[target[b]] - mx - logf(red[0]));
}

__global__ void loss_merge_kernel(float* __restrict__ loss_out)
{
    int lane = threadIdx.x;
    float v = (lane < B_) ? g_nll[lane] : 0.0f;
    #pragma unroll
    for (int off = 16; off; off >>= 1)
        v += __shfl_xor_sync(0xFFFFFFFFu, v, off);
    if (lane == 0) loss_out[0] = v / (float)B_;
}

// ---------------------------------------------------------------------------
extern "C" void kernel_launch(void* const* d_in, const int* in_sizes, int n_in,
                              void* d_out, int out_size)
{
    const int*   x       = (const int*)  d_in[0];
    const int*   target  = (const int*)  d_in[1];
    const float* embed_w = (const float*)d_in[2];
    const float* conv_w  = (const float*)d_in[3];
    const float* conv_b  = (const float*)d_in[4];
    const float* U_w     = (const float*)d_in[5];
    const float* fc_w    = (const float*)d_in[6];
    const float* fc_b    = (const float*)d_in[7];
    float* out = (float*)d_out;   // [0..15999] logits, [16000] loss

    static int smem_set = 0;
    if (!smem_set) {
        cudaFuncSetAttribute(conv_kernel,
                             cudaFuncAttributeMaxDynamicSharedMemorySize, CV_SMEM);
        cudaFuncSetAttribute(attn_kernel,
                             cudaFuncAttributeMaxDynamicSharedMemorySize, AT_SMEM);
        smem_set = 1;
    }

    // 1) producers: fp16 embeddings + weights (+ fragment-ordered attn A)
    embed_kernel<<<dim3(L_ / 8, B_), 256>>>(x, embed_w);
    wtrans_kernel<<<(F_ * E_ + 255) / 256, 256>>>(conv_w);
    wfrag_kernel<<<(16 * 16 * 8 * 32) / 256, 256>>>(U_w, fc_w);

    // 2) conv as 3 shifted K=128 GEMMs -> hcH (fp16)
    conv_kernel<<<dim3(L_ / BM, F_ / BN, B_), 256, CV_SMEM>>>(conv_b);

    // 3) attn GEMM with fused softmax partials
    attn_kernel<<<dim3(L_ / BN, MP_ / BM, B_), 256, AT_SMEM>>>();

    // 4) merge partials -> logits
    part_reduce_kernel<<<B_ * Y_, 32>>>(fc_b, out);

    // 5) cross-entropy loss (parallel per-batch + tiny merge)
    nll_kernel<<<B_, 256>>>(out, target);
    loss_merge_kernel<<<1, 32>>>(out + B_ * Y_);
}

// round 10
// speedup vs baseline: 1.2210x; 1.2210x over previous
#include <cuda_runtime.h>
#include <cuda_fp16.h>
#include <math.h>

#define B_  16
#define L_  4096
#define E_  128
#define F_  256
#define Y_  1000
#define YP_ 1024
#define MP_ 2048             /* padded, interleaved attn M */

#define BM  128
#define BN  128
#define BK  64               /* halves per K chunk */
#define SROWH 72             /* smem row stride in halves (144B, conflict-free) */
#define STAGEH (BM * SROWH)  /* halves per stage per matrix = 9216 */
#define NSTAGE 3
#define SMEM_BYTES (2 * NSTAGE * STAGEH * 2)   /* A + B, 3 stages = 110592 B */

// Scratch (static __device__ arrays; allocation-free per harness rules)
__device__ __align__(128) __half g_embH[(size_t)B_ * L_ * E_];  // fp16 embeddings
__device__ __align__(128) __half g_wH  [3 * F_ * E_];           // fp16 conv_w [kw][f][e]
__device__ __align__(128) __half g_w2H [(size_t)MP_ * F_];      // interleaved [U;fc] rows
__device__ __align__(128) __half g_hcH [(size_t)B_ * L_ * F_];  // conv out fp16 [b][l][f]
__device__ __align__(128) float  g_part[(size_t)B_ * YP_ * 64 * 3]; // (m,Z,S) partials
__device__ float g_nll[B_];

// ---------------------------------------------------------------------------
__device__ __forceinline__ unsigned smem_u32(const void* p) {
    unsigned a;
    asm("{ .reg .u64 t; cvta.to.shared.u64 t, %1; cvt.u32.u64 %0, t; }"
        : "=r"(a) : "l"(p));
    return a;
}
__device__ __forceinline__ void cp_async16(unsigned dst, const void* src, int src_bytes) {
    asm volatile("cp.async.cg.shared.global [%0], [%1], 16, %2;"
                 :: "r"(dst), "l"(src), "r"(src_bytes));
}
__device__ __forceinline__ void cp_commit() {
    asm volatile("cp.async.commit_group;");
}
__device__ __forceinline__ void ldsm4(unsigned* r, unsigned addr) {
    asm volatile("ldmatrix.sync.aligned.m8n8.x4.shared.b16 {%0,%1,%2,%3}, [%4];"
                 : "=r"(r[0]), "=r"(r[1]), "=r"(r[2]), "=r"(r[3]) : "r"(addr));
}
__device__ __forceinline__ void mma16816(float* d, const unsigned* a, const unsigned* b) {
    asm volatile(
        "mma.sync.aligned.m16n8k16.row.col.f32.f16.f16.f32 "
        "{%0,%1,%2,%3}, {%4,%5,%6,%7}, {%8,%9}, {%0,%1,%2,%3};"
        : "+f"(d[0]), "+f"(d[1]), "+f"(d[2]), "+f"(d[3])
        : "r"(a[0]), "r"(a[1]), "r"(a[2]), "r"(a[3]), "r"(b[0]), "r"(b[1]));
}

// ---------------------------------------------------------------------------
// Kernel 1 (fused producers): blocks [0,8192) embed gather; [8192,8320) conv_w
// transpose; [8320,8832) interleaved weight stack. All fp16-rounded.
// ---------------------------------------------------------------------------
__global__ void prep_kernel(const int* __restrict__ x,
                            const float* __restrict__ embed_w,
                            const float* __restrict__ conv_w,
                            const float* __restrict__ U_w,
                            const float* __restrict__ fc_w)
{
    int blk = blockIdx.x;
    if (blk < 8192) {
        // ---- embedding gather: 8 l's per block, b = blk / 512 ----
        int b = blk >> 9;
        int l = (blk & 511) * 8 + (threadIdx.x >> 5);
        int q = threadIdx.x & 31;
        int xi = x[b * L_ + l];
        float4 v = ((const float4*)(embed_w + (size_t)xi * E_))[q];
        __half2 h01 = __floats2half2_rn(v.x, v.y);
        __half2 h23 = __floats2half2_rn(v.z, v.w);
        uint2 u;
        u.x = *(unsigned*)&h01;
        u.y = *(unsigned*)&h23;
        ((uint2*)(g_embH + ((size_t)b * L_ + l) * E_))[q] = u;
    } else if (blk < 8320) {
        // ---- conv_w transpose+round (F,E,3) -> wH[kw][f][e] ----
        int i = (blk - 8192) * 256 + threadIdx.x;
        if (i < F_ * E_) {
            int f = i / E_, e = i % E_;
            #pragma unroll
            for (int kw = 0; kw < 3; kw++)
                g_wH[((size_t)kw * F_ + f) * E_ + e] =
                    __float2half_rn(conv_w[((size_t)f * E_ + e) * 3 + kw]);
        }
    } else {
        // ---- interleaved weight stack: row 2y = U_w[y], row 2y+1 = fc_w[y] ----
        int i = (blk - 8320) * 256 + threadIdx.x;   // over MP_*F_/4 = 131072
        if (i < MP_ * F_ / 4) {
            int r = i / (F_ / 4), c4 = i % (F_ / 4);
            float4 v = make_float4(0.f, 0.f, 0.f, 0.f);
            if (r < 2 * Y_) {
                int y = r >> 1;
                const float* src = (r & 1) ? fc_w : U_w;
                v = ((const float4*)(src + (size_t)y * F_))[c4];
            }
            __half2 h01 = __floats2half2_rn(v.x, v.y);
            __half2 h23 = __floats2half2_rn(v.z, v.w);
            uint2 u;
            u.x = *(unsigned*)&h01;
            u.y = *(unsigned*)&h23;
            ((uint2*)(g_w2H + (size_t)r * F_))[c4] = u;
        }
    }
}

// ---------------------------------------------------------------------------
// Kernel 2/3 (R8-proven): fp16 m16n8k16 GEMM, 128x128 tile, 8 warps (4M x 2N),
// warp tile 32x64, BK=64 chunks, 3-stage cp.async, ONE __syncthreads per chunk.
// mode 0 (conv): C[l,f] = sum_kw sum_e embH[l+kw-1,e]*wH[kw][f][e]; +bias,relu
// mode 1 (attn): C[m,l] = w2H[m,:] . hcH[l,:]; fused online-softmax partials
// ---------------------------------------------------------------------------
__global__ __launch_bounds__(256)
void hgemm_kernel(const float* __restrict__ bias, int mode)
{
    extern __shared__ __align__(16) char smem[];
    unsigned aBase = smem_u32(smem);
    unsigned bBase = aBase + NSTAGE * STAGEH * 2;

    int tid  = threadIdx.x;
    int wid  = tid >> 5, lane = tid & 31;
    int g    = lane >> 2, tig = lane & 3;
    int lq   = lane >> 3, lr  = lane & 7;      // ldmatrix quad / row
    int wm   = wid >> 1,  wn  = wid & 1;       // warp grid 4M x 2N
    int b    = blockIdx.z;

    int m0, n0, nchunks;
    if (mode == 0) { m0 = blockIdx.x * BM; n0 = blockIdx.y * BN; nchunks = 6; }
    else           { m0 = blockIdx.y * BM; n0 = blockIdx.x * BN; nchunks = 4; }

    // loader: 2 threads per row, 32 halves (4x16B) each
    int lrow  = tid >> 1;
    int lcolh = (tid & 1) * 32;

    float d[2][8][4];
    #pragma unroll
    for (int mi = 0; mi < 2; mi++)
        #pragma unroll
        for (int ni = 0; ni < 8; ni++)
            #pragma unroll
            for (int q = 0; q < 4; q++) d[mi][ni][q] = 0.0f;

    auto prefetch = [&](int c) {
        int st = c % NSTAGE;
        const __half* ap;
        const __half* bp;
        int abytes = 16;
        if (mode == 0) {
            int kw = c >> 1, ek = (c & 1) * BK;
            int lsrc = m0 + lrow + kw - 1;
            bool av = ((unsigned)lsrc < (unsigned)L_);
            abytes = av ? 16 : 0;
            ap = g_embH + ((size_t)b * L_ + (av ? lsrc : 0)) * E_ + ek + lcolh;
            bp = g_wH + ((size_t)kw * F_ + n0 + lrow) * E_ + ek + lcolh;
        } else {
            ap = g_w2H + (size_t)(m0 + lrow) * F_ + c * BK + lcolh;
            bp = g_hcH + ((size_t)b * L_ + n0 + lrow) * F_ + c * BK + lcolh;
        }
        unsigned da = aBase + (st * STAGEH + lrow * SROWH + lcolh) * 2;
        unsigned db = bBase + (st * STAGEH + lrow * SROWH + lcolh) * 2;
        #pragma unroll
        for (int j = 0; j < 4; j++) {
            cp_async16(da + j * 16, ap + j * 8, abytes);
            cp_async16(db + j * 16, bp + j * 8, 16);
        }
    };

    prefetch(0);
    cp_commit();
    prefetch(1);
    cp_commit();

    // per-warp ldmatrix smem offsets (stage-relative, bytes)
    unsigned aOffs[2], bOffs[4];
    #pragma unroll
    for (int mi = 0; mi < 2; mi++) {
        int row = wm * 32 + mi * 16 + (lq & 1) * 8 + lr;
        aOffs[mi] = (row * SROWH + (lq >> 1) * 8) * 2;
    }
    #pragma unroll
    for (int ti = 0; ti < 4; ti++) {
        int row = wn * 64 + ti * 16 + (lq >> 1) * 8 + lr;
        bOffs[ti] = (row * SROWH + (lq & 1) * 8) * 2;
    }

    for (int c = 0; c < nchunks; c++) {
        if (c + 1 < nchunks) asm volatile("cp.async.wait_group 1;");
        else                 asm volatile("cp.async.wait_group 0;");
        __syncthreads();    // chunk c resident; buf[(c+2)%3] free (read at iter c-1)

        if (c + 2 < nchunks) {
            prefetch(c + 2);
            cp_commit();
        }

        int st = c % NSTAGE;
        unsigned Ab = aBase + st * STAGEH * 2;
        unsigned Bb = bBase + st * STAGEH * 2;

        #pragma unroll
        for (int kk = 0; kk < 4; kk++) {
            unsigned af[2][4];
            #pragma unroll
            for (int mi = 0; mi < 2; mi++)
                ldsm4(af[mi], Ab + aOffs[mi] + kk * 32);
            unsigned bf[4][4];
            #pragma unroll
            for (int ti = 0; ti < 4; ti++)
                ldsm4(bf[ti], Bb + bOffs[ti] + kk * 32);
            #pragma unroll
            for (int mi = 0; mi < 2; mi++)
                #pragma unroll
                for (int ni = 0; ni < 8; ni++)
                    mma16816(d[mi][ni], af[mi], &bf[ni >> 1][(ni & 1) * 2]);
        }
    }

    // ------------------------- epilogue ------------------------------------
    if (mode == 0) {
        #pragma unroll
        for (int mi = 0; mi < 2; mi++) {
            int row = m0 + wm * 32 + mi * 16 + g;
            #pragma unroll
            for (int ni = 0; ni < 8; ni++) {
                int col = n0 + wn * 64 + ni * 8 + tig * 2;
                float b0 = bias[col], b1 = bias[col + 1];
                __half2 v0 = __floats2half2_rn(fmaxf(d[mi][ni][0] + b0, 0.f),
                                               fmaxf(d[mi][ni][1] + b1, 0.f));
                __half2 v1 = __floats2half2_rn(fmaxf(d[mi][ni][2] + b0, 0.f),
                                               fmaxf(d[mi][ni][3] + b1, 0.f));
                *(__half2*)(g_hcH + ((size_t)b * L_ + row) * F_ + col)     = v0;
                *(__half2*)(g_hcH + ((size_t)b * L_ + row + 8) * F_ + col) = v1;
            }
        }
    } else {
        // rows interleaved: even m = s (U_w), odd m = t (fc_w).
        int p = blockIdx.x * 2 + wn;        // 64-l chunk index (0..63)
        #pragma unroll
        for (int mi = 0; mi < 2; mi++) {
            float td[8][4];
            #pragma unroll
            for (int ni = 0; ni < 8; ni++)
                #pragma unroll
                for (int q = 0; q < 4; q++)
                    td[ni][q] = __shfl_down_sync(0xFFFFFFFFu, d[mi][ni][q], 4);

            if ((g & 1) == 0) {
                #pragma unroll
                for (int h = 0; h < 2; h++) {
                    float mm = -1e30f, Z = 0.f, S = 0.f;
                    #pragma unroll
                    for (int ni = 0; ni < 8; ni++) {
                        #pragma unroll
                        for (int cq = 0; cq < 2; cq++) {
                            float sv = d[mi][ni][h * 2 + cq];
                            float tv = td[ni][h * 2 + cq];
                            if (sv > mm) {
                                float r = __expf(mm - sv);
                                Z *= r; S *= r; mm = sv;
                            }
                            float e = __expf(sv - mm);
                            Z += e; S += e * tv;
                        }
                    }
                    const unsigned qmask = 0x0F0F0F0Fu;
                    #pragma unroll
                    for (int off = 1; off <= 2; off <<= 1) {
                        float m2 = __shfl_xor_sync(qmask, mm, off);
                        float Z2 = __shfl_xor_sync(qmask, Z, off);
                        float S2 = __shfl_xor_sync(qmask, S, off);
                        float mn = fmaxf(mm, m2);
                        float r1 = __expf(mm - mn), r2 = __expf(m2 - mn);
                        Z = Z * r1 + Z2 * r2;
                        S = S * r1 + S2 * r2;
                        mm = mn;
                    }
                    if (tig == 0) {
                        int y = (m0 + wm * 32 + mi * 16 + g + 8 * h) >> 1;
                        float* dst = g_part + ((size_t)(b * YP_ + y) * 64 + p) * 3;
                        dst[0] = mm; dst[1] = Z; dst[2] = S;
                    }
                }
            }
        }
    }
}

// ---------------------------------------------------------------------------
// Kernel 4: merge 64 softmax partials per (b,y) -> logits.
// 256-thread blocks, one warp per (b,y), 8 per block. grid = 2000.
// ---------------------------------------------------------------------------
__global__ void part_reduce_kernel(const float* __restrict__ fc_b,
                                   float* __restrict__ out_logit)
{
    int idx = blockIdx.x * 8 + (threadIdx.x >> 5);   // 0..15999
    int b = idx / Y_, y = idx % Y_;
    const float* pp = g_part + ((size_t)(b * YP_ + y) * 64) * 3;
    int lane = threadIdx.x & 31;

    float m = pp[lane * 3], Z = pp[lane * 3 + 1], S = pp[lane * 3 + 2];
    {
        float m2 = pp[(lane + 32) * 3], Z2 = pp[(lane + 32) * 3 + 1], S2 = pp[(lane + 32) * 3 + 2];
        float mn = fmaxf(m, m2);
        float r1 = __expf(m - mn), r2 = __expf(m2 - mn);
        Z = Z * r1 + Z2 * r2; S = S * r1 + S2 * r2; m = mn;
    }
    #pragma unroll
    for (int off = 16; off; off >>= 1) {
        float m2 = __shfl_xor_sync(0xFFFFFFFFu, m, off);
        float Z2 = __shfl_xor_sync(0xFFFFFFFFu, Z, off);
        float S2 = __shfl_xor_sync(0xFFFFFFFFu, S, off);
        float mn = fmaxf(m, m2);
        float r1 = __expf(m - mn), r2 = __expf(m2 - mn);
        Z = Z * r1 + Z2 * r2; S = S * r1 + S2 * r2; m = mn;
    }
    if (lane == 0) out_logit[b * Y_ + y] = S / Z + fc_b[y];
}

// ---------------------------------------------------------------------------
// Kernel 5a/5b: cross-entropy loss (per-batch + merge)
// ---------------------------------------------------------------------------
__global__ void nll_kernel(const float* __restrict__ logit,
                           const int* __restrict__ target)
{
    __shared__ float red[256];
    int b = blockIdx.x;
    int tid = threadIdx.x;
    const float* lr = logit + b * Y_;

    float mx = -1e30f;
    for (int i = tid; i < Y_; i += 256) mx = fmaxf(mx, lr[i]);
    red[tid] = mx; __syncthreads();
    for (int s = 128; s; s >>= 1) {
        if (tid < s) red[tid] = fmaxf(red[tid], red[tid + s]);
        __syncthreads();
    }
    mx = red[0]; __syncthreads();

    float se = 0.0f;
    for (int i = tid; i < Y_; i += 256) se += expf(lr[i] - mx);
    red[tid] = se; __syncthreads();
    for (int s = 128; s; s >>= 1) {
        if (tid < s) red[tid] += red[tid + s];
        __syncthreads();
    }
    if (tid == 0)
        g_nll[b] = -(lr[target[b]] - mx - logf(red[0]));
}

__global__ void loss_merge_kernel(float* __restrict__ loss_out)
{
    int lane = threadIdx.x;
    float v = (lane < B_) ? g_nll[lane] : 0.0f;
    #pragma unroll
    for (int off = 16; off; off >>= 1)
        v += __shfl_xor_sync(0xFFFFFFFFu, v, off);
    if (lane == 0) loss_out[0] = v / (float)B_;
}

// ---------------------------------------------------------------------------
extern "C" void kernel_launch(void* const* d_in, const int* in_sizes, int n_in,
                              void* d_out, int out_size)
{
    const int*   x       = (const int*)  d_in[0];
    const int*   target  = (const int*)  d_in[1];
    const float* embed_w = (const float*)d_in[2];
    const float* conv_w  = (const float*)d_in[3];
    const float* conv_b  = (const float*)d_in[4];
    const float* U_w     = (const float*)d_in[5];
    const float* fc_w    = (const float*)d_in[6];
    const float* fc_b    = (const float*)d_in[7];
    float* out = (float*)d_out;   // [0..15999] logits, [16000] loss

    static int smem_set = 0;
    if (!smem_set) {
        cudaFuncSetAttribute(hgemm_kernel,
                             cudaFuncAttributeMaxDynamicSharedMemorySize, SMEM_BYTES);
        smem_set = 1;
    }

    // 1) fused producers: fp16 embeddings + conv weights + stacked attn weights
    prep_kernel<<<8832, 256>>>(x, embed_w, conv_w, U_w, fc_w);

    // 2) conv as 3 shifted K=128 GEMMs -> hcH (fp16)
    hgemm_kernel<<<dim3(L_ / BM, F_ / BN, B_), 256, SMEM_BYTES>>>(conv_b, /*mode=*/0);

    // 3) attn GEMM with fused softmax partials
    hgemm_kernel<<<dim3(L_ / BN, MP_ / BM, B_), 256, SMEM_BYTES>>>(nullptr, /*mode=*/1);

    // 4) merge partials -> logits
    part_reduce_kernel<<<(B_ * Y_) / 8, 256>>>(fc_b, out);

    // 5) cross-entropy loss (parallel per-batch + tiny merge)
    nll_kernel<<<B_, 256>>>(out, target);
    loss_merge_kernel<<<1, 32>>>(out + B_ * Y_);
}

// round 11
// speedup vs baseline: 1.3168x; 1.0785x over previous
#include <cuda_runtime.h>
#include <cuda_fp16.h>
#include <math.h>

#define B_  16
#define L_  4096
#define E_  128
#define F_  256
#define Y_  1000
#define YP_ 1024
#define MP_ 2048             /* padded, interleaved attn M */

#define BM  128
#define BN  128
#define BK  64               /* halves per K chunk */
#define SROWH 72             /* A-staging row stride in halves (144B) */
#define STAGEH (BM * SROWH)  /* halves per stage per matrix = 9216 */
#define NSTAGE 3
#define CV_SMEM (2 * NSTAGE * STAGEH * 2)   /* conv: A+B, 3 stages = 110592 B */

/* attn: B resident (128 x 264 halves) + A 2-stage (128 x 72 halves each) */
#define SROWB 264
#define AT_BH (BN * SROWB)                   /* 33792 halves */
#define AT_SMEM ((AT_BH + 2 * STAGEH) * 2)   /* 104448 B */

// Scratch (static __device__ arrays; allocation-free per harness rules)
__device__ __align__(128) __half g_embH[(size_t)B_ * L_ * E_];  // fp16 embeddings
__device__ __align__(128) __half g_wH  [3 * F_ * E_];           // fp16 conv_w [kw][f][e]
__device__ __align__(128) __half g_w2H [(size_t)MP_ * F_];      // interleaved [U;fc] rows
__device__ __align__(128) __half g_hcH [(size_t)B_ * L_ * F_];  // conv out fp16 [b][l][f]
__device__ __align__(128) float  g_part[(size_t)B_ * YP_ * 64 * 3]; // (m,Z,S) partials
__device__ float g_nll[B_];

// ---------------------------------------------------------------------------
__device__ __forceinline__ unsigned smem_u32(const void* p) {
    unsigned a;
    asm("{ .reg .u64 t; cvta.to.shared.u64 t, %1; cvt.u32.u64 %0, t; }"
        : "=r"(a) : "l"(p));
    return a;
}
__device__ __forceinline__ void cp_async16(unsigned dst, const void* src, int src_bytes) {
    asm volatile("cp.async.cg.shared.global [%0], [%1], 16, %2;"
                 :: "r"(dst), "l"(src), "r"(src_bytes));
}
__device__ __forceinline__ void cp_commit() {
    asm volatile("cp.async.commit_group;");
}
__device__ __forceinline__ void ldsm4(unsigned* r, unsigned addr) {
    asm volatile("ldmatrix.sync.aligned.m8n8.x4.shared.b16 {%0,%1,%2,%3}, [%4];"
                 : "=r"(r[0]), "=r"(r[1]), "=r"(r[2]), "=r"(r[3]) : "r"(addr));
}
__device__ __forceinline__ void mma16816(float* d, const unsigned* a, const unsigned* b) {
    asm volatile(
        "mma.sync.aligned.m16n8k16.row.col.f32.f16.f16.f32 "
        "{%0,%1,%2,%3}, {%4,%5,%6,%7}, {%8,%9}, {%0,%1,%2,%3};"
        : "+f"(d[0]), "+f"(d[1]), "+f"(d[2]), "+f"(d[3])
        : "r"(a[0]), "r"(a[1]), "r"(a[2]), "r"(a[3]), "r"(b[0]), "r"(b[1]));
}

// ---------------------------------------------------------------------------
// Kernel 1 (fused producers): blocks [0,8192) embed gather; [8192,8320) conv_w
// transpose; [8320,8832) interleaved weight stack. All fp16-rounded.
// ---------------------------------------------------------------------------
__global__ void prep_kernel(const int* __restrict__ x,
                            const float* __restrict__ embed_w,
                            const float* __restrict__ conv_w,
                            const float* __restrict__ U_w,
                            const float* __restrict__ fc_w)
{
    int blk = blockIdx.x;
    if (blk < 8192) {
        int b = blk >> 9;
        int l = (blk & 511) * 8 + (threadIdx.x >> 5);
        int q = threadIdx.x & 31;
        int xi = x[b * L_ + l];
        float4 v = ((const float4*)(embed_w + (size_t)xi * E_))[q];
        __half2 h01 = __floats2half2_rn(v.x, v.y);
        __half2 h23 = __floats2half2_rn(v.z, v.w);
        uint2 u;
        u.x = *(unsigned*)&h01;
        u.y = *(unsigned*)&h23;
        ((uint2*)(g_embH + ((size_t)b * L_ + l) * E_))[q] = u;
    } else if (blk < 8320) {
        int i = (blk - 8192) * 256 + threadIdx.x;
        if (i < F_ * E_) {
            int f = i / E_, e = i % E_;
            #pragma unroll
            for (int kw = 0; kw < 3; kw++)
                g_wH[((size_t)kw * F_ + f) * E_ + e] =
                    __float2half_rn(conv_w[((size_t)f * E_ + e) * 3 + kw]);
        }
    } else {
        int i = (blk - 8320) * 256 + threadIdx.x;
        if (i < MP_ * F_ / 4) {
            int r = i / (F_ / 4), c4 = i % (F_ / 4);
            float4 v = make_float4(0.f, 0.f, 0.f, 0.f);
            if (r < 2 * Y_) {
                int y = r >> 1;
                const float* src = (r & 1) ? fc_w : U_w;
                v = ((const float4*)(src + (size_t)y * F_))[c4];
            }
            __half2 h01 = __floats2half2_rn(v.x, v.y);
            __half2 h23 = __floats2half2_rn(v.z, v.w);
            uint2 u;
            u.x = *(unsigned*)&h01;
            u.y = *(unsigned*)&h23;
            ((uint2*)(g_w2H + (size_t)r * F_))[c4] = u;
        }
    }
}

// ---------------------------------------------------------------------------
// Kernel 2 (R8-proven conv): 128x128 tile, 8 warps, BK=64, 3-stage cp.async.
// C[l,f] = sum_kw sum_e embH[l+kw-1,e]*wH[kw][f][e]; +bias, relu -> hcH
// ---------------------------------------------------------------------------
__global__ __launch_bounds__(256)
void conv_kernel(const float* __restrict__ bias)
{
    extern __shared__ __align__(16) char smem[];
    unsigned aBase = smem_u32(smem);
    unsigned bBase = aBase + NSTAGE * STAGEH * 2;

    int tid  = threadIdx.x;
    int wid  = tid >> 5, lane = tid & 31;
    int g    = lane >> 2, tig = lane & 3;
    int lq   = lane >> 3, lr  = lane & 7;
    int wm   = wid >> 1,  wn  = wid & 1;
    int b    = blockIdx.z;
    int m0   = blockIdx.x * BM, n0 = blockIdx.y * BN;
    const int nchunks = 6;

    int lrow  = tid >> 1;
    int lcolh = (tid & 1) * 32;

    float d[2][8][4];
    #pragma unroll
    for (int mi = 0; mi < 2; mi++)
        #pragma unroll
        for (int ni = 0; ni < 8; ni++)
            #pragma unroll
            for (int q = 0; q < 4; q++) d[mi][ni][q] = 0.0f;

    auto prefetch = [&](int c) {
        int st = c % NSTAGE;
        int kw = c >> 1, ek = (c & 1) * BK;
        int lsrc = m0 + lrow + kw - 1;
        bool av = ((unsigned)lsrc < (unsigned)L_);
        int abytes = av ? 16 : 0;
        const __half* ap = g_embH + ((size_t)b * L_ + (av ? lsrc : 0)) * E_ + ek + lcolh;
        const __half* bp = g_wH + ((size_t)kw * F_ + n0 + lrow) * E_ + ek + lcolh;
        unsigned da = aBase + (st * STAGEH + lrow * SROWH + lcolh) * 2;
        unsigned db = bBase + (st * STAGEH + lrow * SROWH + lcolh) * 2;
        #pragma unroll
        for (int j = 0; j < 4; j++) {
            cp_async16(da + j * 16, ap + j * 8, abytes);
            cp_async16(db + j * 16, bp + j * 8, 16);
        }
    };

    prefetch(0); cp_commit();
    prefetch(1); cp_commit();

    unsigned aOffs[2], bOffs[4];
    #pragma unroll
    for (int mi = 0; mi < 2; mi++) {
        int row = wm * 32 + mi * 16 + (lq & 1) * 8 + lr;
        aOffs[mi] = (row * SROWH + (lq >> 1) * 8) * 2;
    }
    #pragma unroll
    for (int ti = 0; ti < 4; ti++) {
        int row = wn * 64 + ti * 16 + (lq >> 1) * 8 + lr;
        bOffs[ti] = (row * SROWH + (lq & 1) * 8) * 2;
    }

    for (int c = 0; c < nchunks; c++) {
        if (c + 1 < nchunks) asm volatile("cp.async.wait_group 1;");
        else                 asm volatile("cp.async.wait_group 0;");
        __syncthreads();
        if (c + 2 < nchunks) { prefetch(c + 2); cp_commit(); }

        int st = c % NSTAGE;
        unsigned Ab = aBase + st * STAGEH * 2;
        unsigned Bb = bBase + st * STAGEH * 2;

        #pragma unroll
        for (int kk = 0; kk < 4; kk++) {
            unsigned af[2][4];
            #pragma unroll
            for (int mi = 0; mi < 2; mi++)
                ldsm4(af[mi], Ab + aOffs[mi] + kk * 32);
            unsigned bf[4][4];
            #pragma unroll
            for (int ti = 0; ti < 4; ti++)
                ldsm4(bf[ti], Bb + bOffs[ti] + kk * 32);
            #pragma unroll
            for (int mi = 0; mi < 2; mi++)
                #pragma unroll
                for (int ni = 0; ni < 8; ni++)
                    mma16816(d[mi][ni], af[mi], &bf[ni >> 1][(ni & 1) * 2]);
        }
    }

    #pragma unroll
    for (int mi = 0; mi < 2; mi++) {
        int row = m0 + wm * 32 + mi * 16 + g;
        #pragma unroll
        for (int ni = 0; ni < 8; ni++) {
            int col = n0 + wn * 64 + ni * 8 + tig * 2;
            float b0 = bias[col], b1 = bias[col + 1];
            __half2 v0 = __floats2half2_rn(fmaxf(d[mi][ni][0] + b0, 0.f),
                                           fmaxf(d[mi][ni][1] + b1, 0.f));
            __half2 v1 = __floats2half2_rn(fmaxf(d[mi][ni][2] + b0, 0.f),
                                           fmaxf(d[mi][ni][3] + b1, 0.f));
            *(__half2*)(g_hcH + ((size_t)b * L_ + row) * F_ + col)     = v0;
            *(__half2*)(g_hcH + ((size_t)b * L_ + row + 8) * F_ + col) = v1;
        }
    }
}

// ---------------------------------------------------------------------------
// Kernel 3: attn GEMM with B RESIDENT in smem. Each block owns one l-tile
// (128 cols of hcH, full K=256) and loops over 4 m-tiles, streaming A
// (2-stage, BK=64, distance-1 prefetch). Fused online-softmax partials.
// grid = (L/128, 4, B_) = 2048 blocks.
// ---------------------------------------------------------------------------
__global__ __launch_bounds__(256)
void attn_kernel()
{
    extern __shared__ __align__(16) char smem[];
    unsigned bBase = smem_u32(smem);                 // B: 128 x SROWB halves
    unsigned aBase = bBase + AT_BH * 2;              // A: 2 x STAGEH halves

    int tid  = threadIdx.x;
    int wid  = tid >> 5, lane = tid & 31;
    int g    = lane >> 2, tig = lane & 3;
    int lq   = lane >> 3, lr  = lane & 7;
    int wm   = wid >> 1,  wn  = wid & 1;
    int b    = blockIdx.z;
    int n0   = blockIdx.x * BN;
    int mg0  = blockIdx.y * 4 * BM;                  // m-group base

    int lrow  = tid >> 1;
    int lcolh = (tid & 1) * 32;

    // ---- issue B tile load: 128 rows x 256 halves, 2 threads/row ----
    {
        const __half* bp = g_hcH + ((size_t)b * L_ + n0 + lrow) * F_ + (tid & 1) * 128;
        unsigned db = bBase + (lrow * SROWB + (tid & 1) * 128) * 2;
        #pragma unroll
        for (int j = 0; j < 16; j++)
            cp_async16(db + j * 16, bp + j * 8, 16);
    }
    cp_commit();

    // ---- A chunk stream: q = mtile*4 + kc, 16 chunks total ----
    auto prefetchA = [&](int q) {
        int i = q >> 2, kc = q & 3;
        const __half* ap = g_w2H + (size_t)(mg0 + i * BM + lrow) * F_ + kc * BK + lcolh;
        unsigned da = aBase + ((q & 1) * STAGEH + lrow * SROWH + lcolh) * 2;
        #pragma unroll
        for (int j = 0; j < 4; j++)
            cp_async16(da + j * 16, ap + j * 8, 16);
    };

    prefetchA(0);
    cp_commit();

    unsigned aOffs[2], bOffs[4];
    #pragma unroll
    for (int mi = 0; mi < 2; mi++) {
        int row = wm * 32 + mi * 16 + (lq & 1) * 8 + lr;
        aOffs[mi] = (row * SROWH + (lq >> 1) * 8) * 2;
    }
    #pragma unroll
    for (int ti = 0; ti < 4; ti++) {
        int row = wn * 64 + ti * 16 + (lq >> 1) * 8 + lr;
        bOffs[ti] = (row * SROWB + (lq & 1) * 8) * 2;
    }

    int p = blockIdx.x * 2 + wn;        // 64-l chunk index (0..63)
    float d[2][8][4];

    for (int q = 0; q < 16; q++) {
        int kc = q & 3;
        if (kc == 0) {
            #pragma unroll
            for (int mi = 0; mi < 2; mi++)
                #pragma unroll
                for (int ni = 0; ni < 8; ni++)
                    #pragma unroll
                    for (int u = 0; u < 4; u++) d[mi][ni][u] = 0.0f;
        }

        asm volatile("cp.async.wait_group 0;");
        __syncthreads();                 // A stage q&1 + (q==0: B) resident
        if (q + 1 < 16) { prefetchA(q + 1); cp_commit(); }

        unsigned Ab = aBase + (q & 1) * STAGEH * 2;
        unsigned Bc = bBase + kc * BK * 2;   // column offset within B rows

        #pragma unroll
        for (int kk = 0; kk < 4; kk++) {
            unsigned af[2][4];
            #pragma unroll
            for (int mi = 0; mi < 2; mi++)
                ldsm4(af[mi], Ab + aOffs[mi] + kk * 32);
            unsigned bf[4][4];
            #pragma unroll
            for (int ti = 0; ti < 4; ti++)
                ldsm4(bf[ti], Bc + bOffs[ti] + kk * 32);
            #pragma unroll
            for (int mi = 0; mi < 2; mi++)
                #pragma unroll
                for (int ni = 0; ni < 8; ni++)
                    mma16816(d[mi][ni], af[mi], &bf[ni >> 1][(ni & 1) * 2]);
        }

        if (kc == 3) {
            // epilogue for m-tile q>>2 (rows interleaved: even=s, odd=t)
            int m0 = mg0 + (q >> 2) * BM;
            #pragma unroll
            for (int mi = 0; mi < 2; mi++) {
                float td[8][4];
                #pragma unroll
                for (int ni = 0; ni < 8; ni++)
                    #pragma unroll
                    for (int u = 0; u < 4; u++)
                        td[ni][u] = __shfl_down_sync(0xFFFFFFFFu, d[mi][ni][u], 4);

                if ((g & 1) == 0) {
                    #pragma unroll
                    for (int h = 0; h < 2; h++) {
                        float mm = -1e30f, Z = 0.f, S = 0.f;
                        #pragma unroll
                        for (int ni = 0; ni < 8; ni++) {
                            #pragma unroll
                            for (int cq = 0; cq < 2; cq++) {
                                float sv = d[mi][ni][h * 2 + cq];
                                float tv = td[ni][h * 2 + cq];
                                if (sv > mm) {
                                    float r = __expf(mm - sv);
                                    Z *= r; S *= r; mm = sv;
                                }
                                float e = __expf(sv - mm);
                                Z += e; S += e * tv;
                            }
                        }
                        const unsigned qmask = 0x0F0F0F0Fu;
                        #pragma unroll
                        for (int off = 1; off <= 2; off <<= 1) {
                            float m2 = __shfl_xor_sync(qmask, mm, off);
                            float Z2 = __shfl_xor_sync(qmask, Z, off);
                            float S2 = __shfl_xor_sync(qmask, S, off);
                            float mn = fmaxf(mm, m2);
                            float r1 = __expf(mm - mn), r2 = __expf(m2 - mn);
                            Z = Z * r1 + Z2 * r2;
                            S = S * r1 + S2 * r2;
                            mm = mn;
                        }
                        if (tig == 0) {
                            int y = (m0 + wm * 32 + mi * 16 + g + 8 * h) >> 1;
                            float* dst = g_part + ((size_t)(b * YP_ + y) * 64 + p) * 3;
                            dst[0] = mm; dst[1] = Z; dst[2] = S;
                        }
                    }
                }
            }
        }
    }
}

// ---------------------------------------------------------------------------
// Kernel 4: merge 64 softmax partials per (b,y) -> logits.
// ---------------------------------------------------------------------------
__global__ void part_reduce_kernel(const float* __restrict__ fc_b,
                                   float* __restrict__ out_logit)
{
    int idx = blockIdx.x * 8 + (threadIdx.x >> 5);   // 0..15999
    int b = idx / Y_, y = idx % Y_;
    const float* pp = g_part + ((size_t)(b * YP_ + y) * 64) * 3;
    int lane = threadIdx.x & 31;

    float m = pp[lane * 3], Z = pp[lane * 3 + 1], S = pp[lane * 3 + 2];
    {
        float m2 = pp[(lane + 32) * 3], Z2 = pp[(lane + 32) * 3 + 1], S2 = pp[(lane + 32) * 3 + 2];
        float mn = fmaxf(m, m2);
        float r1 = __expf(m - mn), r2 = __expf(m2 - mn);
        Z = Z * r1 + Z2 * r2; S = S * r1 + S2 * r2; m = mn;
    }
    #pragma unroll
    for (int off = 16; off; off >>= 1) {
        float m2 = __shfl_xor_sync(0xFFFFFFFFu, m, off);
        float Z2 = __shfl_xor_sync(0xFFFFFFFFu, Z, off);
        float S2 = __shfl_xor_sync(0xFFFFFFFFu, S, off);
        float mn = fmaxf(m, m2);
        float r1 = __expf(m - mn), r2 = __expf(m2 - mn);
        Z = Z * r1 + Z2 * r2; S = S * r1 + S2 * r2; m = mn;
    }
    if (lane == 0) out_logit[b * Y_ + y] = S / Z + fc_b[y];
}

// ---------------------------------------------------------------------------
// Kernel 5a/5b: cross-entropy loss (per-batch + merge)
// ---------------------------------------------------------------------------
__global__ void nll_kernel(const float* __restrict__ logit,
                           const int* __restrict__ target)
{
    __shared__ float red[256];
    int b = blockIdx.x;
    int tid = threadIdx.x;
    const float* lr = logit + b * Y_;

    float mx = -1e30f;
    for (int i = tid; i < Y_; i += 256) mx = fmaxf(mx, lr[i]);
    red[tid] = mx; __syncthreads();
    for (int s = 128; s; s >>= 1) {
        if (tid < s) red[tid] = fmaxf(red[tid], red[tid + s]);
        __syncthreads();
    }
    mx = red[0]; __syncthreads();

    float se = 0.0f;
    for (int i = tid; i < Y_; i += 256) se += expf(lr[i] - mx);
    red[tid] = se; __syncthreads();
    for (int s = 128; s; s >>= 1) {
        if (tid < s) red[tid] += red[tid + s];
        __syncthreads();
    }
    if (tid == 0)
        g_nll[b] = -(lr[target[b]] - mx - logf(red[0]));
}

__global__ void loss_merge_kernel(float* __restrict__ loss_out)
{
    int lane = threadIdx.x;
    float v = (lane < B_) ? g_nll[lane] : 0.0f;
    #pragma unroll
    for (int off = 16; off; off >>= 1)
        v += __shfl_xor_sync(0xFFFFFFFFu, v, off);
    if (lane == 0) loss_out[0] = v / (float)B_;
}

// ---------------------------------------------------------------------------
extern "C" void kernel_launch(void* const* d_in, const int* in_sizes, int n_in,
                              void* d_out, int out_size)
{
    const int*   x       = (const int*)  d_in[0];
    const int*   target  = (const int*)  d_in[1];
    const float* embed_w = (const float*)d_in[2];
    const float* conv_w  = (const float*)d_in[3];
    const float* conv_b  = (const float*)d_in[4];
    const float* U_w     = (const float*)d_in[5];
    const float* fc_w    = (const float*)d_in[6];
    const float* fc_b    = (const float*)d_in[7];
    float* out = (float*)d_out;   // [0..15999] logits, [16000] loss

    static int smem_set = 0;
    if (!smem_set) {
        cudaFuncSetAttribute(conv_kernel,
                             cudaFuncAttributeMaxDynamicSharedMemorySize, CV_SMEM);
        cudaFuncSetAttribute(attn_kernel,
                             cudaFuncAttributeMaxDynamicSharedMemorySize, AT_SMEM);
        smem_set = 1;
    }

    // 1) fused producers
    prep_kernel<<<8832, 256>>>(x, embed_w, conv_w, U_w, fc_w);

    // 2) conv as 3 shifted K=128 GEMMs -> hcH (fp16)
    conv_kernel<<<dim3(L_ / BM, F_ / BN, B_), 256, CV_SMEM>>>(conv_b);

    // 3) attn GEMM, B-resident, fused softmax partials
    attn_kernel<<<dim3(L_ / BN, 4, B_), 256, AT_SMEM>>>();

    // 4) merge partials -> logits
    part_reduce_kernel<<<(B_ * Y_) / 8, 256>>>(fc_b, out);

    // 5) cross-entropy loss
    nll_kernel<<<B_, 256>>>(out, target);
    loss_merge_kernel<<<1, 32>>>(out + B_ * Y_);
}